// round 14
// baseline (speedup 1.0000x reference)
#include <cuda_runtime.h>
#include <cuda_fp16.h>
#include <math.h>
#include <stdint.h>

// Problem constants
#define B_  4
#define T_  2048
#define C_  1024
#define NH_ 16
#define D_  64
#define M_  (B_ * T_)                 // 8192 rows
#define INV_TP 0.08838834764831845f  // 1/sqrt(2*D)
#define LOG2E 1.4426950408889634f
#define LN_EPS 1e-5f

// Scratch (device globals; no allocation allowed)
__device__ __half g_Xh[M_ * C_];
__device__ __half g_Wqh[C_ * C_];
__device__ __half g_Wkh[C_ * C_];
__device__ __half g_Wvh[C_ * C_];
__device__ __half g_Qh[M_ * C_];
__device__ __half g_Kh[M_ * C_];
__device__ __half g_Vh[M_ * C_];
__device__ float  g_A[M_ * C_];

// ---------------------------------------------------------------------------
// Helpers
// ---------------------------------------------------------------------------
__device__ __forceinline__ void mma_f16(float c[4],
                                        uint32_t a0, uint32_t a1,
                                        uint32_t a2, uint32_t a3,
                                        uint32_t b0, uint32_t b1) {
    asm volatile(
        "mma.sync.aligned.m16n8k16.row.col.f32.f16.f16.f32 "
        "{%0,%1,%2,%3},{%4,%5,%6,%7},{%8,%9},{%0,%1,%2,%3};"
        : "+f"(c[0]), "+f"(c[1]), "+f"(c[2]), "+f"(c[3])
        : "r"(a0), "r"(a1), "r"(a2), "r"(a3), "r"(b0), "r"(b1));
}

__device__ __forceinline__ void ldsm_x4(uint32_t& r0, uint32_t& r1,
                                        uint32_t& r2, uint32_t& r3,
                                        uint32_t addr) {
    asm volatile("ldmatrix.sync.aligned.m8n8.x4.shared.b16 {%0,%1,%2,%3},[%4];"
                 : "=r"(r0), "=r"(r1), "=r"(r2), "=r"(r3) : "r"(addr));
}
__device__ __forceinline__ void ldsm_x4t(uint32_t& r0, uint32_t& r1,
                                         uint32_t& r2, uint32_t& r3,
                                         uint32_t addr) {
    asm volatile("ldmatrix.sync.aligned.m8n8.x4.trans.shared.b16 {%0,%1,%2,%3},[%4];"
                 : "=r"(r0), "=r"(r1), "=r"(r2), "=r"(r3) : "r"(addr));
}

__device__ __forceinline__ float ex2f(float x) {
    float y;
    asm("ex2.approx.ftz.f32 %0, %1;" : "=f"(y) : "f"(x));
    return y;
}

__device__ __forceinline__ uint32_t packh2(float x, float y) {
    __half2 h = __floats2half2_rn(x, y);
    return *(uint32_t*)&h;
}

__device__ __forceinline__ void cp16(uint32_t saddr, const void* gptr) {
    asm volatile("cp.async.cg.shared.global [%0], [%1], 16;"
                 :: "r"(saddr), "l"(gptr));
}
#define CP_COMMIT() asm volatile("cp.async.commit_group;")
#define CP_WAIT1()  asm volatile("cp.async.wait_group 1;")
#define CP_WAIT0()  asm volatile("cp.async.wait_group 0;")

// ---------------------------------------------------------------------------
// Fused fp32 -> fp16 conversion: x, Wq, Wk, Wv in ONE launch.
// ---------------------------------------------------------------------------
#define NX4 (M_ * C_ / 4)   // 2097152
#define NW4 (C_ * C_ / 4)   // 262144

__global__ void __launch_bounds__(256)
cvt_all_kernel(const float* __restrict__ x,  const float* __restrict__ Wq,
               const float* __restrict__ Wk, const float* __restrict__ Wv) {
    int i = blockIdx.x * blockDim.x + threadIdx.x;
    const float* src;
    __half* dst;
    int j;
    if (i < NX4)                { src = x;  dst = g_Xh;  j = i; }
    else if (i < NX4 + NW4)     { src = Wq; dst = g_Wqh; j = i - NX4; }
    else if (i < NX4 + 2 * NW4) { src = Wk; dst = g_Wkh; j = i - NX4 - NW4; }
    else if (i < NX4 + 3 * NW4) { src = Wv; dst = g_Wvh; j = i - NX4 - 2 * NW4; }
    else return;
    float4 v = ((const float4*)src)[j];
    ((__half2*)dst)[2 * j]     = __floats2half2_rn(v.x, v.y);
    ((__half2*)dst)[2 * j + 1] = __floats2half2_rn(v.z, v.w);
}

// ---------------------------------------------------------------------------
// Fused QKV GEMM-NT (fp16 in, fp32 accum). Block 128x128, K-chunk 64,
// 128 threads (4 warps, 64x64 warp tiles), 2-stage cp.async.
// B-fragments loaded in n-tile PAIRS via ldmatrix.x4. Row pitch 144B.
// ---------------------------------------------------------------------------
#define GBM 128
#define GBN 128
#define GBK 64
#define GPH 72
#define QTILE_B (GBM * GPH * 2)       // 18432 bytes per tile

__global__ void __launch_bounds__(128)
qkv_kernel(const __half* __restrict__ xh,
           const __half* __restrict__ Wq, const __half* __restrict__ Wk,
           const __half* __restrict__ Wv,
           __half* __restrict__ Qo, __half* __restrict__ Ko,
           __half* __restrict__ Vo) {
    extern __shared__ char smraw[];
    const uint32_t As_u = (uint32_t)__cvta_generic_to_shared(smraw);
    const uint32_t Bs_u = As_u + 2 * QTILE_B;

    const int z = blockIdx.z;
    const __half* W = (z == 0) ? Wq : (z == 1) ? Wk : Wv;
    __half* Cm      = (z == 0) ? Qo : (z == 1) ? Ko : Vo;

    const int tid  = threadIdx.x;
    const int warp = tid >> 5;
    const int lane = tid & 31;
    const int g = lane >> 2;
    const int q = lane & 3;
    const int wm = (warp & 1) * 64;
    const int wn = (warp >> 1) * 64;
    const int bm = blockIdx.y * GBM;
    const int bn = blockIdx.x * GBN;

    // ldmatrix lane offsets (bytes)
    const uint32_t laneA  = (uint32_t)((lane & 15) * 144 + (lane >> 4) * 16);
    // x4 pair-of-B-tiles: lanes 0-7 rows r+0..7 k-lo, 8-15 k-hi, 16-23 rows+8
    const uint32_t laneB4 = (uint32_t)(((lane & 7) + ((lane >> 4) << 3)) * 144 +
                                       (((lane >> 3) & 1) * 16));

    float cc[4][8][4];
    #pragma unroll
    for (int mt = 0; mt < 4; mt++)
        #pragma unroll
        for (int nt = 0; nt < 8; nt++)
            #pragma unroll
            for (int e = 0; e < 4; e++) cc[mt][nt][e] = 0.f;

    auto copy_tile = [&](int st, int kt) {
        const int k0 = kt * GBK;
        const uint32_t sa = As_u + (uint32_t)st * QTILE_B;
        const uint32_t sb = Bs_u + (uint32_t)st * QTILE_B;
        #pragma unroll
        for (int i = 0; i < 8; i++) {
            int idx = i * 128 + tid;
            int r = idx >> 3;
            int c8 = (idx & 7) * 8;
            cp16(sa + (uint32_t)(r * 144 + (idx & 7) * 16),
                 xh + (size_t)(bm + r) * C_ + k0 + c8);
            cp16(sb + (uint32_t)(r * 144 + (idx & 7) * 16),
                 W + (size_t)(bn + r) * C_ + k0 + c8);
        }
    };

    const int NT = C_ / GBK;   // 16
    copy_tile(0, 0);
    CP_COMMIT();

    for (int kt = 0; kt < NT; kt++) {
        if (kt + 1 < NT) {
            copy_tile((kt + 1) & 1, kt + 1);
            CP_COMMIT();
            CP_WAIT1();
        } else {
            CP_WAIT0();
        }
        __syncthreads();

        const uint32_t a_s = As_u + (uint32_t)((kt & 1)) * QTILE_B;
        const uint32_t b_s = Bs_u + (uint32_t)((kt & 1)) * QTILE_B;

        #pragma unroll
        for (int ks = 0; ks < 4; ks++) {
            uint32_t af[4][4];
            #pragma unroll
            for (int mt = 0; mt < 4; mt++)
                ldsm_x4(af[mt][0], af[mt][1], af[mt][2], af[mt][3],
                        a_s + (uint32_t)((wm + mt * 16) * 144 + ks * 32) + laneA);
            uint32_t bf[8][2];
            #pragma unroll
            for (int np = 0; np < 4; np++)
                ldsm_x4(bf[2 * np][0], bf[2 * np][1],
                        bf[2 * np + 1][0], bf[2 * np + 1][1],
                        b_s + (uint32_t)((wn + np * 16) * 144 + ks * 32) + laneB4);
            #pragma unroll
            for (int mt = 0; mt < 4; mt++)
                #pragma unroll
                for (int nt = 0; nt < 8; nt++)
                    mma_f16(cc[mt][nt], af[mt][0], af[mt][1], af[mt][2],
                            af[mt][3], bf[nt][0], bf[nt][1]);
        }
        __syncthreads();
    }

    #pragma unroll
    for (int mt = 0; mt < 4; mt++) {
        int r0 = bm + wm + mt * 16 + g;
        #pragma unroll
        for (int nt = 0; nt < 8; nt++) {
            int col = bn + wn + nt * 8 + 2 * q;
            *(__half2*)(Cm + (size_t)r0 * C_ + col) =
                __floats2half2_rn(cc[mt][nt][0], cc[mt][nt][1]);
            *(__half2*)(Cm + (size_t)(r0 + 8) * C_ + col) =
                __floats2half2_rn(cc[mt][nt][2], cc[mt][nt][3]);
        }
    }
}

// ---------------------------------------------------------------------------
// Flash attention (causal), fp16 MMA, P in registers.
// K B-frags via ldmatrix.x4 pairs; V B-frags via ldmatrix.x4.trans pairs.
// Q tile 128 x D=64, KV tiles 64 double-buffered, 4 warps (32 rows each).
// ---------------------------------------------------------------------------
#define PS_B (128 * 144)     // 18432 bytes (Q staging only)
#define KT_B (64 * 144)      // 9216 bytes per KV stage per matrix

__global__ void __launch_bounds__(128)
attn_kernel(const __half* __restrict__ Q, const __half* __restrict__ K,
            const __half* __restrict__ V, float* __restrict__ O_) {
    extern __shared__ char smb[];
    const uint32_t Ps_u = (uint32_t)__cvta_generic_to_shared(smb);
    const uint32_t Ks_u = Ps_u + PS_B;         // 2 x 64 x 72
    const uint32_t Vs_u = Ks_u + 2 * KT_B;     // 2 x 64 x 72

    const int qt  = (gridDim.x - 1) - blockIdx.x;   // heavy blocks first
    const int bh  = blockIdx.y;
    const int b   = bh / NH_;
    const int h   = bh % NH_;
    const int tid  = threadIdx.x;
    const int warp = tid >> 5;
    const int lane = tid & 31;
    const int g = lane >> 2;
    const int q = lane & 3;
    const int wr = warp * 32;

    const uint32_t laneA  = (uint32_t)((lane & 15) * 144 + (lane >> 4) * 16);
    const uint32_t laneB4 = (uint32_t)(((lane & 7) + ((lane >> 4) << 3)) * 144 +
                                       (((lane >> 3) & 1) * 16));
    // x4.trans for V: r0/r1 = k-lo/k-hi of col-group c, r2/r3 = of col-group c+1
    const uint32_t laneT4 = (uint32_t)(((lane & 7) + (((lane >> 3) & 1) << 3)) * 144 +
                                       ((lane >> 4) << 4));

    const size_t base = ((size_t)b * T_) * C_ + (size_t)h * D_;
    const int gqr = qt * 128;

    auto copy_kv = [&](int st, int kt) {
        const uint32_t sk = Ks_u + (uint32_t)st * KT_B;
        const uint32_t sv = Vs_u + (uint32_t)st * KT_B;
        #pragma unroll
        for (int i = 0; i < 4; i++) {
            int idx = i * 128 + tid;
            int r = idx >> 3;
            int c8 = (idx & 7) * 8;
            cp16(sk + (uint32_t)(r * 144 + (idx & 7) * 16),
                 K + base + (size_t)(kt * 64 + r) * C_ + c8);
            cp16(sv + (uint32_t)(r * 144 + (idx & 7) * 16),
                 V + base + (size_t)(kt * 64 + r) * C_ + c8);
        }
    };

    copy_kv(0, 0);
    CP_COMMIT();

    // stage Q (scaled into log2 domain)
    const __half2 qsh = __float2half2_rn(INV_TP * LOG2E);
    for (int i = 0; i < 8; i++) {
        int idx = i * 128 + tid;
        int r = idx >> 3;
        int d8 = (idx & 7) * 8;
        uint4 raw = *(const uint4*)(Q + base + (size_t)(gqr + r) * C_ + d8);
        __half2* hp = (__half2*)&raw;
        hp[0] = __hmul2(hp[0], qsh);
        hp[1] = __hmul2(hp[1], qsh);
        hp[2] = __hmul2(hp[2], qsh);
        hp[3] = __hmul2(hp[3], qsh);
        *(uint4*)((char*)smb + r * 144 + d8 * 2) = raw;
    }
    __syncthreads();

    // register-resident Q fragments (4 k-steps of 16)
    uint32_t qf[2][4][4];
    #pragma unroll
    for (int mt = 0; mt < 2; mt++)
        #pragma unroll
        for (int ks = 0; ks < 4; ks++)
            ldsm_x4(qf[mt][ks][0], qf[mt][ks][1], qf[mt][ks][2], qf[mt][ks][3],
                    Ps_u + (uint32_t)((wr + mt * 16) * 144 + ks * 32) + laneA);

    float o[2][8][4];
    #pragma unroll
    for (int mt = 0; mt < 2; mt++)
        #pragma unroll
        for (int nt = 0; nt < 8; nt++)
            #pragma unroll
            for (int e = 0; e < 4; e++) o[mt][nt][e] = 0.f;
    float mrow[2][2], lrow[2][2];
    #pragma unroll
    for (int mt = 0; mt < 2; mt++) {
        mrow[mt][0] = -1e30f; mrow[mt][1] = -1e30f;
        lrow[mt][0] = 0.f;    lrow[mt][1] = 0.f;
    }

    const int nkv = 2 * qt + 2;
    for (int kt = 0; kt < nkv; kt++) {
        if (kt + 1 < nkv) {
            copy_kv((kt + 1) & 1, kt + 1);
            CP_COMMIT();
            CP_WAIT1();
        } else {
            CP_WAIT0();
        }
        __syncthreads();

        const uint32_t k_s = Ks_u + (uint32_t)((kt & 1)) * KT_B;
        const uint32_t v_s = Vs_u + (uint32_t)((kt & 1)) * KT_B;
        const int c0 = kt * 64;
        const bool active = (c0 <= gqr + wr + 31);

        if (active) {
            // S = Q K^T  (A regs, K B-frag pairs via x4)
            float s[2][8][4];
            #pragma unroll
            for (int mt = 0; mt < 2; mt++)
                #pragma unroll
                for (int nt = 0; nt < 8; nt++)
                    #pragma unroll
                    for (int e = 0; e < 4; e++) s[mt][nt][e] = 0.f;

            #pragma unroll
            for (int ks = 0; ks < 4; ks++) {
                uint32_t bk[8][2];
                #pragma unroll
                for (int np = 0; np < 4; np++)
                    ldsm_x4(bk[2 * np][0], bk[2 * np][1],
                            bk[2 * np + 1][0], bk[2 * np + 1][1],
                            k_s + (uint32_t)(np * 16 * 144 + ks * 32) + laneB4);
                #pragma unroll
                for (int nt = 0; nt < 8; nt++) {
                    mma_f16(s[0][nt], qf[0][ks][0], qf[0][ks][1],
                            qf[0][ks][2], qf[0][ks][3], bk[nt][0], bk[nt][1]);
                    mma_f16(s[1][nt], qf[1][ks][0], qf[1][ks][1],
                            qf[1][ks][2], qf[1][ks][3], bk[nt][0], bk[nt][1]);
                }
            }

            // causal mask
            if (c0 + 63 > gqr + wr) {
                #pragma unroll
                for (int mt = 0; mt < 2; mt++)
                    #pragma unroll
                    for (int nt = 0; nt < 8; nt++)
                        #pragma unroll
                        for (int e = 0; e < 4; e++) {
                            int r = gqr + wr + mt * 16 + g + ((e >= 2) ? 8 : 0);
                            int c = c0 + nt * 8 + 2 * q + (e & 1);
                            if (c > r) s[mt][nt][e] = -1e30f;
                        }
            }

            // online softmax (log2 domain)
            #pragma unroll
            for (int mt = 0; mt < 2; mt++) {
                float mx0 = -1e30f, mx1 = -1e30f;
                #pragma unroll
                for (int nt = 0; nt < 8; nt++) {
                    mx0 = fmaxf(mx0, fmaxf(s[mt][nt][0], s[mt][nt][1]));
                    mx1 = fmaxf(mx1, fmaxf(s[mt][nt][2], s[mt][nt][3]));
                }
                mx0 = fmaxf(mx0, __shfl_xor_sync(0xffffffffu, mx0, 1));
                mx0 = fmaxf(mx0, __shfl_xor_sync(0xffffffffu, mx0, 2));
                mx1 = fmaxf(mx1, __shfl_xor_sync(0xffffffffu, mx1, 1));
                mx1 = fmaxf(mx1, __shfl_xor_sync(0xffffffffu, mx1, 2));
                float mn0 = fmaxf(mrow[mt][0], mx0);
                float mn1 = fmaxf(mrow[mt][1], mx1);
                float corr0 = ex2f(mrow[mt][0] - mn0);
                float corr1 = ex2f(mrow[mt][1] - mn1);
                mrow[mt][0] = mn0; mrow[mt][1] = mn1;

                float rs0 = 0.f, rs1 = 0.f;
                #pragma unroll
                for (int nt = 0; nt < 8; nt++) {
                    float p0 = ex2f(s[mt][nt][0] - mn0);
                    float p1 = ex2f(s[mt][nt][1] - mn0);
                    float p2 = ex2f(s[mt][nt][2] - mn1);
                    float p3 = ex2f(s[mt][nt][3] - mn1);
                    s[mt][nt][0] = p0; s[mt][nt][1] = p1;
                    s[mt][nt][2] = p2; s[mt][nt][3] = p3;
                    rs0 += p0 + p1; rs1 += p2 + p3;
                }
                rs0 += __shfl_xor_sync(0xffffffffu, rs0, 1);
                rs0 += __shfl_xor_sync(0xffffffffu, rs0, 2);
                rs1 += __shfl_xor_sync(0xffffffffu, rs1, 1);
                rs1 += __shfl_xor_sync(0xffffffffu, rs1, 2);
                lrow[mt][0] = lrow[mt][0] * corr0 + rs0;
                lrow[mt][1] = lrow[mt][1] * corr1 + rs1;
                #pragma unroll
                for (int nt = 0; nt < 8; nt++) {
                    o[mt][nt][0] *= corr0; o[mt][nt][1] *= corr0;
                    o[mt][nt][2] *= corr1; o[mt][nt][3] *= corr1;
                }
            }

            // O += P @ V  — P A-fragments from S registers; V pairs via x4.trans
            #pragma unroll
            for (int ks = 0; ks < 4; ks++) {
                uint32_t a[2][4];
                #pragma unroll
                for (int mt = 0; mt < 2; mt++) {
                    a[mt][0] = packh2(s[mt][2 * ks][0],     s[mt][2 * ks][1]);
                    a[mt][1] = packh2(s[mt][2 * ks][2],     s[mt][2 * ks][3]);
                    a[mt][2] = packh2(s[mt][2 * ks + 1][0], s[mt][2 * ks + 1][1]);
                    a[mt][3] = packh2(s[mt][2 * ks + 1][2], s[mt][2 * ks + 1][3]);
                }
                #pragma unroll
                for (int np = 0; np < 4; np++) {
                    uint32_t bv[4];
                    ldsm_x4t(bv[0], bv[1], bv[2], bv[3],
                             v_s + (uint32_t)(ks * 16 * 144 + np * 32) + laneT4);
                    int nt0 = 2 * np;
                    mma_f16(o[0][nt0], a[0][0], a[0][1], a[0][2], a[0][3],
                            bv[0], bv[1]);
                    mma_f16(o[1][nt0], a[1][0], a[1][1], a[1][2], a[1][3],
                            bv[0], bv[1]);
                    mma_f16(o[0][nt0 + 1], a[0][0], a[0][1], a[0][2], a[0][3],
                            bv[2], bv[3]);
                    mma_f16(o[1][nt0 + 1], a[1][0], a[1][1], a[1][2], a[1][3],
                            bv[2], bv[3]);
                }
            }
        }
        __syncthreads();
    }

    // epilogue: normalize and store (fp32)
    #pragma unroll
    for (int mt = 0; mt < 2; mt++) {
        float inv0 = 1.f / lrow[mt][0];
        float inv1 = 1.f / lrow[mt][1];
        int r0 = gqr + wr + mt * 16 + g;
        #pragma unroll
        for (int nt = 0; nt < 8; nt++) {
            int col = nt * 8 + 2 * q;
            *(float2*)(O_ + base + (size_t)r0 * C_ + col) =
                make_float2(o[mt][nt][0] * inv0, o[mt][nt][1] * inv0);
            *(float2*)(O_ + base + (size_t)(r0 + 8) * C_ + col) =
                make_float2(o[mt][nt][2] * inv1, o[mt][nt][3] * inv1);
        }
    }
}

// ---------------------------------------------------------------------------
// Residual + LayerNorm. One block per row.
// ---------------------------------------------------------------------------
__global__ void __launch_bounds__(256)
ln_kernel(const float* __restrict__ x, const float* __restrict__ attn,
          const float* __restrict__ gamma, const float* __restrict__ beta,
          float* __restrict__ out) {
    __shared__ float buf[C_];
    __shared__ float s1[8], s2[8];

    const int row = blockIdx.x;
    const int t = threadIdx.x;
    const float4 xa = ((const float4*)(x    + (size_t)row * C_))[t];
    const float4 aa = ((const float4*)(attn + (size_t)row * C_))[t];
    float4 y;
    y.x = xa.x + aa.x; y.y = xa.y + aa.y; y.z = xa.z + aa.z; y.w = xa.w + aa.w;
    ((float4*)buf)[t] = y;

    float lsum = y.x + y.y + y.z + y.w;
    float lsq  = y.x * y.x + y.y * y.y + y.z * y.z + y.w * y.w;
    #pragma unroll
    for (int off = 16; off; off >>= 1) {
        lsum += __shfl_xor_sync(0xffffffffu, lsum, off);
        lsq  += __shfl_xor_sync(0xffffffffu, lsq,  off);
    }
    const int wid = t >> 5, lane = t & 31;
    if (lane == 0) { s1[wid] = lsum; s2[wid] = lsq; }
    __syncthreads();
    if (t == 0) {
        float a = 0.f, b2 = 0.f;
        #pragma unroll
        for (int i = 0; i < 8; i++) { a += s1[i]; b2 += s2[i]; }
        s1[0] = a; s2[0] = b2;
    }
    __syncthreads();
    const float mean = s1[0] * (1.f / C_);
    const float var  = s2[0] * (1.f / C_) - mean * mean;
    const float inv  = rsqrtf(var + LN_EPS);

    const float4 yv = ((const float4*)buf)[t];
    const float4 gg = ((const float4*)gamma)[t];
    const float4 bb = ((const float4*)beta)[t];
    float4 oo;
    oo.x = (yv.x - mean) * inv * gg.x + bb.x;
    oo.y = (yv.y - mean) * inv * gg.y + bb.y;
    oo.z = (yv.z - mean) * inv * gg.z + bb.z;
    oo.w = (yv.w - mean) * inv * gg.w + bb.w;
    ((float4*)(out + (size_t)row * C_))[t] = oo;
}

// ---------------------------------------------------------------------------
// Launcher
// ---------------------------------------------------------------------------
extern "C" void kernel_launch(void* const* d_in, const int* in_sizes, int n_in,
                              void* d_out, int out_size) {
    const float* x     = (const float*)d_in[0];
    // d_in[1] = mask (bool) — causal, applied analytically in-kernel
    const float* Wq    = (const float*)d_in[2];
    const float* Wk    = (const float*)d_in[3];
    const float* Wv    = (const float*)d_in[4];
    const float* gamma = (const float*)d_in[5];
    const float* beta  = (const float*)d_in[6];
    float* out = (float*)d_out;

    __half *xh, *wqh, *wkh, *wvh, *qh, *kh, *vh;
    float* ab;
    cudaGetSymbolAddress((void**)&xh,  g_Xh);
    cudaGetSymbolAddress((void**)&wqh, g_Wqh);
    cudaGetSymbolAddress((void**)&wkh, g_Wkh);
    cudaGetSymbolAddress((void**)&wvh, g_Wvh);
    cudaGetSymbolAddress((void**)&qh,  g_Qh);
    cudaGetSymbolAddress((void**)&kh,  g_Kh);
    cudaGetSymbolAddress((void**)&vh,  g_Vh);
    cudaGetSymbolAddress((void**)&ab,  g_A);

    // fp32 -> fp16 prologue (single fused launch)
    const int ntot = NX4 + 3 * NW4;
    cvt_all_kernel<<<(ntot + 255) / 256, 256>>>(x, Wq, Wk, Wv);

    const int gemm_smem = 4 * QTILE_B;  // 73728 B
    cudaFuncSetAttribute(qkv_kernel, cudaFuncAttributeMaxDynamicSharedMemorySize,
                         gemm_smem);
    qkv_kernel<<<dim3(C_ / GBN, M_ / GBM, 3), 128, gemm_smem>>>(
        xh, wqh, wkh, wvh, qh, kh, vh);

    const int attn_smem = PS_B + 4 * KT_B;  // 55296 B
    cudaFuncSetAttribute(attn_kernel, cudaFuncAttributeMaxDynamicSharedMemorySize,
                         attn_smem);
    attn_kernel<<<dim3(T_ / 128, B_ * NH_), 128, attn_smem>>>(qh, kh, vh, ab);

    ln_kernel<<<M_, 256>>>(x, ab, gamma, beta, out);
}

// round 15
// speedup vs baseline: 1.0428x; 1.0428x over previous
#include <cuda_runtime.h>
#include <cuda_fp16.h>
#include <math.h>
#include <stdint.h>

// Problem constants
#define B_  4
#define T_  2048
#define C_  1024
#define NH_ 16
#define D_  64
#define M_  (B_ * T_)                 // 8192 rows
#define INV_TP 0.08838834764831845f  // 1/sqrt(2*D)
#define LOG2E 1.4426950408889634f
#define LN_EPS 1e-5f

// Scratch (device globals; no allocation allowed)
__device__ __half g_Xh[M_ * C_];
__device__ __half g_Wqh[C_ * C_];
__device__ __half g_Wkh[C_ * C_];
__device__ __half g_Wvh[C_ * C_];
__device__ __half g_Qh[M_ * C_];
__device__ __half g_Kh[M_ * C_];
__device__ __half g_Vh[M_ * C_];
__device__ float  g_A[M_ * C_];

// ---------------------------------------------------------------------------
// Helpers
// ---------------------------------------------------------------------------
__device__ __forceinline__ void mma_f16(float c[4],
                                        uint32_t a0, uint32_t a1,
                                        uint32_t a2, uint32_t a3,
                                        uint32_t b0, uint32_t b1) {
    asm volatile(
        "mma.sync.aligned.m16n8k16.row.col.f32.f16.f16.f32 "
        "{%0,%1,%2,%3},{%4,%5,%6,%7},{%8,%9},{%0,%1,%2,%3};"
        : "+f"(c[0]), "+f"(c[1]), "+f"(c[2]), "+f"(c[3])
        : "r"(a0), "r"(a1), "r"(a2), "r"(a3), "r"(b0), "r"(b1));
}

__device__ __forceinline__ void ldsm_x4(uint32_t& r0, uint32_t& r1,
                                        uint32_t& r2, uint32_t& r3,
                                        uint32_t addr) {
    asm volatile("ldmatrix.sync.aligned.m8n8.x4.shared.b16 {%0,%1,%2,%3},[%4];"
                 : "=r"(r0), "=r"(r1), "=r"(r2), "=r"(r3) : "r"(addr));
}
__device__ __forceinline__ void ldsm_x2(uint32_t& r0, uint32_t& r1,
                                        uint32_t addr) {
    asm volatile("ldmatrix.sync.aligned.m8n8.x2.shared.b16 {%0,%1},[%2];"
                 : "=r"(r0), "=r"(r1) : "r"(addr));
}
__device__ __forceinline__ void ldsm_x2t(uint32_t& r0, uint32_t& r1,
                                         uint32_t addr) {
    asm volatile("ldmatrix.sync.aligned.m8n8.x2.trans.shared.b16 {%0,%1},[%2];"
                 : "=r"(r0), "=r"(r1) : "r"(addr));
}

__device__ __forceinline__ float ex2f(float x) {
    float y;
    asm("ex2.approx.ftz.f32 %0, %1;" : "=f"(y) : "f"(x));
    return y;
}

__device__ __forceinline__ uint32_t packh2(float x, float y) {
    __half2 h = __floats2half2_rn(x, y);
    return *(uint32_t*)&h;
}

__device__ __forceinline__ void cp16(uint32_t saddr, const void* gptr) {
    asm volatile("cp.async.cg.shared.global [%0], [%1], 16;"
                 :: "r"(saddr), "l"(gptr));
}
#define CP_COMMIT() asm volatile("cp.async.commit_group;")
#define CP_WAIT1()  asm volatile("cp.async.wait_group 1;")
#define CP_WAIT0()  asm volatile("cp.async.wait_group 0;")

// ---------------------------------------------------------------------------
// Fused fp32 -> fp16 conversion: x, Wq, Wk, Wv in ONE launch.
// ---------------------------------------------------------------------------
#define NX4 (M_ * C_ / 4)   // 2097152
#define NW4 (C_ * C_ / 4)   // 262144

__global__ void __launch_bounds__(256)
cvt_all_kernel(const float* __restrict__ x,  const float* __restrict__ Wq,
               const float* __restrict__ Wk, const float* __restrict__ Wv) {
    int i = blockIdx.x * blockDim.x + threadIdx.x;
    const float* src;
    __half* dst;
    int j;
    if (i < NX4)                { src = x;  dst = g_Xh;  j = i; }
    else if (i < NX4 + NW4)     { src = Wq; dst = g_Wqh; j = i - NX4; }
    else if (i < NX4 + 2 * NW4) { src = Wk; dst = g_Wkh; j = i - NX4 - NW4; }
    else if (i < NX4 + 3 * NW4) { src = Wv; dst = g_Wvh; j = i - NX4 - 2 * NW4; }
    else return;
    float4 v = ((const float4*)src)[j];
    ((__half2*)dst)[2 * j]     = __floats2half2_rn(v.x, v.y);
    ((__half2*)dst)[2 * j + 1] = __floats2half2_rn(v.z, v.w);
}

// ---------------------------------------------------------------------------
// Fused QKV GEMM-NT (fp16 in, fp32 accum) — R12 configuration (proven).
// Block 128x128, K-chunk 64, 128 threads (4 warps, 64x64 warp tiles),
// 2-stage cp.async, per-tile ldmatrix (conflict-free). Row pitch 144B.
// ---------------------------------------------------------------------------
#define GBM 128
#define GBN 128
#define GBK 64
#define GPH 72
#define QTILE_B (GBM * GPH * 2)       // 18432 bytes per tile

__global__ void __launch_bounds__(128)
qkv_kernel(const __half* __restrict__ xh,
           const __half* __restrict__ Wq, const __half* __restrict__ Wk,
           const __half* __restrict__ Wv,
           __half* __restrict__ Qo, __half* __restrict__ Ko,
           __half* __restrict__ Vo) {
    extern __shared__ char smraw[];
    const uint32_t As_u = (uint32_t)__cvta_generic_to_shared(smraw);
    const uint32_t Bs_u = As_u + 2 * QTILE_B;

    const int z = blockIdx.z;
    const __half* W = (z == 0) ? Wq : (z == 1) ? Wk : Wv;
    __half* Cm      = (z == 0) ? Qo : (z == 1) ? Ko : Vo;

    const int tid  = threadIdx.x;
    const int warp = tid >> 5;
    const int lane = tid & 31;
    const int g = lane >> 2;
    const int q = lane & 3;
    const int wm = (warp & 1) * 64;
    const int wn = (warp >> 1) * 64;
    const int bm = blockIdx.y * GBM;
    const int bn = blockIdx.x * GBN;

    const uint32_t laneA = (uint32_t)((lane & 15) * 144 + (lane >> 4) * 16);
    const uint32_t laneB = (uint32_t)((lane & 7) * 144 + ((lane >> 3) & 1) * 16);

    float cc[4][8][4];
    #pragma unroll
    for (int mt = 0; mt < 4; mt++)
        #pragma unroll
        for (int nt = 0; nt < 8; nt++)
            #pragma unroll
            for (int e = 0; e < 4; e++) cc[mt][nt][e] = 0.f;

    auto copy_tile = [&](int st, int kt) {
        const int k0 = kt * GBK;
        const uint32_t sa = As_u + (uint32_t)st * QTILE_B;
        const uint32_t sb = Bs_u + (uint32_t)st * QTILE_B;
        #pragma unroll
        for (int i = 0; i < 8; i++) {
            int idx = i * 128 + tid;
            int r = idx >> 3;
            int c8 = (idx & 7) * 8;
            cp16(sa + (uint32_t)(r * 144 + (idx & 7) * 16),
                 xh + (size_t)(bm + r) * C_ + k0 + c8);
            cp16(sb + (uint32_t)(r * 144 + (idx & 7) * 16),
                 W + (size_t)(bn + r) * C_ + k0 + c8);
        }
    };

    const int NT = C_ / GBK;   // 16
    copy_tile(0, 0);
    CP_COMMIT();

    for (int kt = 0; kt < NT; kt++) {
        if (kt + 1 < NT) {
            copy_tile((kt + 1) & 1, kt + 1);
            CP_COMMIT();
            CP_WAIT1();
        } else {
            CP_WAIT0();
        }
        __syncthreads();

        const uint32_t a_s = As_u + (uint32_t)((kt & 1)) * QTILE_B;
        const uint32_t b_s = Bs_u + (uint32_t)((kt & 1)) * QTILE_B;

        #pragma unroll
        for (int ks = 0; ks < 4; ks++) {
            uint32_t af[4][4];
            #pragma unroll
            for (int mt = 0; mt < 4; mt++)
                ldsm_x4(af[mt][0], af[mt][1], af[mt][2], af[mt][3],
                        a_s + (uint32_t)((wm + mt * 16) * 144 + ks * 32) + laneA);
            uint32_t bf[8][2];
            #pragma unroll
            for (int nt = 0; nt < 8; nt++)
                ldsm_x2(bf[nt][0], bf[nt][1],
                        b_s + (uint32_t)((wn + nt * 8) * 144 + ks * 32) + laneB);
            #pragma unroll
            for (int mt = 0; mt < 4; mt++)
                #pragma unroll
                for (int nt = 0; nt < 8; nt++)
                    mma_f16(cc[mt][nt], af[mt][0], af[mt][1], af[mt][2],
                            af[mt][3], bf[nt][0], bf[nt][1]);
        }
        __syncthreads();
    }

    #pragma unroll
    for (int mt = 0; mt < 4; mt++) {
        int r0 = bm + wm + mt * 16 + g;
        #pragma unroll
        for (int nt = 0; nt < 8; nt++) {
            int col = bn + wn + nt * 8 + 2 * q;
            *(__half2*)(Cm + (size_t)r0 * C_ + col) =
                __floats2half2_rn(cc[mt][nt][0], cc[mt][nt][1]);
            *(__half2*)(Cm + (size_t)(r0 + 8) * C_ + col) =
                __floats2half2_rn(cc[mt][nt][2], cc[mt][nt][3]);
        }
    }
}

// ---------------------------------------------------------------------------
// Flash attention (causal), fp16 MMA + ldmatrix, P in registers — R12 config.
// Q tile 128 x D=64, KV tiles 64 double-buffered, 4 warps (32 rows each).
// ---------------------------------------------------------------------------
#define PS_B (128 * 144)     // 18432 bytes (Q staging only)
#define KT_B (64 * 144)      // 9216 bytes per KV stage per matrix

__global__ void __launch_bounds__(128)
attn_kernel(const __half* __restrict__ Q, const __half* __restrict__ K,
            const __half* __restrict__ V, float* __restrict__ O_) {
    extern __shared__ char smb[];
    const uint32_t Ps_u = (uint32_t)__cvta_generic_to_shared(smb);
    const uint32_t Ks_u = Ps_u + PS_B;         // 2 x 64 x 72
    const uint32_t Vs_u = Ks_u + 2 * KT_B;     // 2 x 64 x 72

    const int qt  = (gridDim.x - 1) - blockIdx.x;   // heavy blocks first
    const int bh  = blockIdx.y;
    const int b   = bh / NH_;
    const int h   = bh % NH_;
    const int tid  = threadIdx.x;
    const int warp = tid >> 5;
    const int lane = tid & 31;
    const int g = lane >> 2;
    const int q = lane & 3;
    const int wr = warp * 32;

    const uint32_t laneA = (uint32_t)((lane & 15) * 144 + (lane >> 4) * 16);
    const uint32_t laneB = (uint32_t)((lane & 7) * 144 + ((lane >> 3) & 1) * 16);
    const uint32_t laneT = (uint32_t)((lane & 15) * 144);   // trans B (V)

    const size_t base = ((size_t)b * T_) * C_ + (size_t)h * D_;
    const int gqr = qt * 128;

    auto copy_kv = [&](int st, int kt) {
        const uint32_t sk = Ks_u + (uint32_t)st * KT_B;
        const uint32_t sv = Vs_u + (uint32_t)st * KT_B;
        #pragma unroll
        for (int i = 0; i < 4; i++) {
            int idx = i * 128 + tid;
            int r = idx >> 3;
            int c8 = (idx & 7) * 8;
            cp16(sk + (uint32_t)(r * 144 + (idx & 7) * 16),
                 K + base + (size_t)(kt * 64 + r) * C_ + c8);
            cp16(sv + (uint32_t)(r * 144 + (idx & 7) * 16),
                 V + base + (size_t)(kt * 64 + r) * C_ + c8);
        }
    };

    copy_kv(0, 0);
    CP_COMMIT();

    // stage Q (scaled into log2 domain)
    const __half2 qsh = __float2half2_rn(INV_TP * LOG2E);
    for (int i = 0; i < 8; i++) {
        int idx = i * 128 + tid;
        int r = idx >> 3;
        int d8 = (idx & 7) * 8;
        uint4 raw = *(const uint4*)(Q + base + (size_t)(gqr + r) * C_ + d8);
        __half2* hp = (__half2*)&raw;
        hp[0] = __hmul2(hp[0], qsh);
        hp[1] = __hmul2(hp[1], qsh);
        hp[2] = __hmul2(hp[2], qsh);
        hp[3] = __hmul2(hp[3], qsh);
        *(uint4*)((char*)smb + r * 144 + d8 * 2) = raw;
    }
    __syncthreads();

    // register-resident Q fragments (4 k-steps of 16)
    uint32_t qf[2][4][4];
    #pragma unroll
    for (int mt = 0; mt < 2; mt++)
        #pragma unroll
        for (int ks = 0; ks < 4; ks++)
            ldsm_x4(qf[mt][ks][0], qf[mt][ks][1], qf[mt][ks][2], qf[mt][ks][3],
                    Ps_u + (uint32_t)((wr + mt * 16) * 144 + ks * 32) + laneA);

    float o[2][8][4];
    #pragma unroll
    for (int mt = 0; mt < 2; mt++)
        #pragma unroll
        for (int nt = 0; nt < 8; nt++)
            #pragma unroll
            for (int e = 0; e < 4; e++) o[mt][nt][e] = 0.f;
    float mrow[2][2], lrow[2][2];
    #pragma unroll
    for (int mt = 0; mt < 2; mt++) {
        mrow[mt][0] = -1e30f; mrow[mt][1] = -1e30f;
        lrow[mt][0] = 0.f;    lrow[mt][1] = 0.f;
    }

    const int nkv = 2 * qt + 2;
    for (int kt = 0; kt < nkv; kt++) {
        if (kt + 1 < nkv) {
            copy_kv((kt + 1) & 1, kt + 1);
            CP_COMMIT();
            CP_WAIT1();
        } else {
            CP_WAIT0();
        }
        __syncthreads();

        const uint32_t k_s = Ks_u + (uint32_t)((kt & 1)) * KT_B;
        const uint32_t v_s = Vs_u + (uint32_t)((kt & 1)) * KT_B;
        const int c0 = kt * 64;
        const bool active = (c0 <= gqr + wr + 31);

        if (active) {
            // S = Q K^T  (A regs, B via ldmatrix; 4 k-steps of 16)
            float s[2][8][4];
            #pragma unroll
            for (int mt = 0; mt < 2; mt++)
                #pragma unroll
                for (int nt = 0; nt < 8; nt++)
                    #pragma unroll
                    for (int e = 0; e < 4; e++) s[mt][nt][e] = 0.f;

            #pragma unroll
            for (int ks = 0; ks < 4; ks++) {
                #pragma unroll
                for (int nt = 0; nt < 8; nt++) {
                    uint32_t b0, b1;
                    ldsm_x2(b0, b1,
                            k_s + (uint32_t)((nt * 8) * 144 + ks * 32) + laneB);
                    mma_f16(s[0][nt], qf[0][ks][0], qf[0][ks][1],
                            qf[0][ks][2], qf[0][ks][3], b0, b1);
                    mma_f16(s[1][nt], qf[1][ks][0], qf[1][ks][1],
                            qf[1][ks][2], qf[1][ks][3], b0, b1);
                }
            }

            // causal mask
            if (c0 + 63 > gqr + wr) {
                #pragma unroll
                for (int mt = 0; mt < 2; mt++)
                    #pragma unroll
                    for (int nt = 0; nt < 8; nt++)
                        #pragma unroll
                        for (int e = 0; e < 4; e++) {
                            int r = gqr + wr + mt * 16 + g + ((e >= 2) ? 8 : 0);
                            int c = c0 + nt * 8 + 2 * q + (e & 1);
                            if (c > r) s[mt][nt][e] = -1e30f;
                        }
            }

            // online softmax (log2 domain)
            #pragma unroll
            for (int mt = 0; mt < 2; mt++) {
                float mx0 = -1e30f, mx1 = -1e30f;
                #pragma unroll
                for (int nt = 0; nt < 8; nt++) {
                    mx0 = fmaxf(mx0, fmaxf(s[mt][nt][0], s[mt][nt][1]));
                    mx1 = fmaxf(mx1, fmaxf(s[mt][nt][2], s[mt][nt][3]));
                }
                mx0 = fmaxf(mx0, __shfl_xor_sync(0xffffffffu, mx0, 1));
                mx0 = fmaxf(mx0, __shfl_xor_sync(0xffffffffu, mx0, 2));
                mx1 = fmaxf(mx1, __shfl_xor_sync(0xffffffffu, mx1, 1));
                mx1 = fmaxf(mx1, __shfl_xor_sync(0xffffffffu, mx1, 2));
                float mn0 = fmaxf(mrow[mt][0], mx0);
                float mn1 = fmaxf(mrow[mt][1], mx1);
                float corr0 = ex2f(mrow[mt][0] - mn0);
                float corr1 = ex2f(mrow[mt][1] - mn1);
                mrow[mt][0] = mn0; mrow[mt][1] = mn1;

                float rs0 = 0.f, rs1 = 0.f;
                #pragma unroll
                for (int nt = 0; nt < 8; nt++) {
                    float p0 = ex2f(s[mt][nt][0] - mn0);
                    float p1 = ex2f(s[mt][nt][1] - mn0);
                    float p2 = ex2f(s[mt][nt][2] - mn1);
                    float p3 = ex2f(s[mt][nt][3] - mn1);
                    s[mt][nt][0] = p0; s[mt][nt][1] = p1;
                    s[mt][nt][2] = p2; s[mt][nt][3] = p3;
                    rs0 += p0 + p1; rs1 += p2 + p3;
                }
                rs0 += __shfl_xor_sync(0xffffffffu, rs0, 1);
                rs0 += __shfl_xor_sync(0xffffffffu, rs0, 2);
                rs1 += __shfl_xor_sync(0xffffffffu, rs1, 1);
                rs1 += __shfl_xor_sync(0xffffffffu, rs1, 2);
                lrow[mt][0] = lrow[mt][0] * corr0 + rs0;
                lrow[mt][1] = lrow[mt][1] * corr1 + rs1;
                #pragma unroll
                for (int nt = 0; nt < 8; nt++) {
                    o[mt][nt][0] *= corr0; o[mt][nt][1] *= corr0;
                    o[mt][nt][2] *= corr1; o[mt][nt][3] *= corr1;
                }
            }

            // O += P @ V  — P A-fragments built directly from S registers
            #pragma unroll
            for (int ks = 0; ks < 4; ks++) {
                uint32_t a[2][4];
                #pragma unroll
                for (int mt = 0; mt < 2; mt++) {
                    a[mt][0] = packh2(s[mt][2 * ks][0],     s[mt][2 * ks][1]);
                    a[mt][1] = packh2(s[mt][2 * ks][2],     s[mt][2 * ks][3]);
                    a[mt][2] = packh2(s[mt][2 * ks + 1][0], s[mt][2 * ks + 1][1]);
                    a[mt][3] = packh2(s[mt][2 * ks + 1][2], s[mt][2 * ks + 1][3]);
                }
                #pragma unroll
                for (int nt = 0; nt < 8; nt++) {
                    uint32_t b0, b1;
                    ldsm_x2t(b0, b1,
                             v_s + (uint32_t)(ks * 16 * 144 + nt * 16) + laneT);
                    mma_f16(o[0][nt], a[0][0], a[0][1], a[0][2], a[0][3], b0, b1);
                    mma_f16(o[1][nt], a[1][0], a[1][1], a[1][2], a[1][3], b0, b1);
                }
            }
        }
        __syncthreads();
    }

    // epilogue: normalize and store (fp32)
    #pragma unroll
    for (int mt = 0; mt < 2; mt++) {
        float inv0 = 1.f / lrow[mt][0];
        float inv1 = 1.f / lrow[mt][1];
        int r0 = gqr + wr + mt * 16 + g;
        #pragma unroll
        for (int nt = 0; nt < 8; nt++) {
            int col = nt * 8 + 2 * q;
            *(float2*)(O_ + base + (size_t)r0 * C_ + col) =
                make_float2(o[mt][nt][0] * inv0, o[mt][nt][1] * inv0);
            *(float2*)(O_ + base + (size_t)(r0 + 8) * C_ + col) =
                make_float2(o[mt][nt][2] * inv1, o[mt][nt][3] * inv1);
        }
    }
}

// ---------------------------------------------------------------------------
// Residual + LayerNorm. One block per row.
// ---------------------------------------------------------------------------
__global__ void __launch_bounds__(256)
ln_kernel(const float* __restrict__ x, const float* __restrict__ attn,
          const float* __restrict__ gamma, const float* __restrict__ beta,
          float* __restrict__ out) {
    __shared__ float buf[C_];
    __shared__ float s1[8], s2[8];

    const int row = blockIdx.x;
    const int t = threadIdx.x;
    const float4 xa = ((const float4*)(x    + (size_t)row * C_))[t];
    const float4 aa = ((const float4*)(attn + (size_t)row * C_))[t];
    float4 y;
    y.x = xa.x + aa.x; y.y = xa.y + aa.y; y.z = xa.z + aa.z; y.w = xa.w + aa.w;
    ((float4*)buf)[t] = y;

    float lsum = y.x + y.y + y.z + y.w;
    float lsq  = y.x * y.x + y.y * y.y + y.z * y.z + y.w * y.w;
    #pragma unroll
    for (int off = 16; off; off >>= 1) {
        lsum += __shfl_xor_sync(0xffffffffu, lsum, off);
        lsq  += __shfl_xor_sync(0xffffffffu, lsq,  off);
    }
    const int wid = t >> 5, lane = t & 31;
    if (lane == 0) { s1[wid] = lsum; s2[wid] = lsq; }
    __syncthreads();
    if (t == 0) {
        float a = 0.f, b2 = 0.f;
        #pragma unroll
        for (int i = 0; i < 8; i++) { a += s1[i]; b2 += s2[i]; }
        s1[0] = a; s2[0] = b2;
    }
    __syncthreads();
    const float mean = s1[0] * (1.f / C_);
    const float var  = s2[0] * (1.f / C_) - mean * mean;
    const float inv  = rsqrtf(var + LN_EPS);

    const float4 yv = ((const float4*)buf)[t];
    const float4 gg = ((const float4*)gamma)[t];
    const float4 bb = ((const float4*)beta)[t];
    float4 oo;
    oo.x = (yv.x - mean) * inv * gg.x + bb.x;
    oo.y = (yv.y - mean) * inv * gg.y + bb.y;
    oo.z = (yv.z - mean) * inv * gg.z + bb.z;
    oo.w = (yv.w - mean) * inv * gg.w + bb.w;
    ((float4*)(out + (size_t)row * C_))[t] = oo;
}

// ---------------------------------------------------------------------------
// Launcher
// ---------------------------------------------------------------------------
extern "C" void kernel_launch(void* const* d_in, const int* in_sizes, int n_in,
                              void* d_out, int out_size) {
    const float* x     = (const float*)d_in[0];
    // d_in[1] = mask (bool) — causal, applied analytically in-kernel
    const float* Wq    = (const float*)d_in[2];
    const float* Wk    = (const float*)d_in[3];
    const float* Wv    = (const float*)d_in[4];
    const float* gamma = (const float*)d_in[5];
    const float* beta  = (const float*)d_in[6];
    float* out = (float*)d_out;

    __half *xh, *wqh, *wkh, *wvh, *qh, *kh, *vh;
    float* ab;
    cudaGetSymbolAddress((void**)&xh,  g_Xh);
    cudaGetSymbolAddress((void**)&wqh, g_Wqh);
    cudaGetSymbolAddress((void**)&wkh, g_Wkh);
    cudaGetSymbolAddress((void**)&wvh, g_Wvh);
    cudaGetSymbolAddress((void**)&qh,  g_Qh);
    cudaGetSymbolAddress((void**)&kh,  g_Kh);
    cudaGetSymbolAddress((void**)&vh,  g_Vh);
    cudaGetSymbolAddress((void**)&ab,  g_A);

    // fp32 -> fp16 prologue (single fused launch)
    const int ntot = NX4 + 3 * NW4;
    cvt_all_kernel<<<(ntot + 255) / 256, 256>>>(x, Wq, Wk, Wv);

    const int gemm_smem = 4 * QTILE_B;  // 73728 B
    cudaFuncSetAttribute(qkv_kernel, cudaFuncAttributeMaxDynamicSharedMemorySize,
                         gemm_smem);
    qkv_kernel<<<dim3(C_ / GBN, M_ / GBM, 3), 128, gemm_smem>>>(
        xh, wqh, wkh, wvh, qh, kh, vh);

    const int attn_smem = PS_B + 4 * KT_B;  // 55296 B
    cudaFuncSetAttribute(attn_kernel, cudaFuncAttributeMaxDynamicSharedMemorySize,
                         attn_smem);
    attn_kernel<<<dim3(T_ / 128, B_ * NH_), 128, attn_smem>>>(qh, kh, vh, ab);

    ln_kernel<<<M_, 256>>>(x, ab, gamma, beta, out);
}

// round 16
// speedup vs baseline: 1.0495x; 1.0064x over previous
#include <cuda_runtime.h>
#include <cuda_fp16.h>
#include <math.h>
#include <stdint.h>

// Problem constants
#define B_  4
#define T_  2048
#define C_  1024
#define NH_ 16
#define D_  64
#define M_  (B_ * T_)                 // 8192 rows
#define INV_TP 0.08838834764831845f  // 1/sqrt(2*D)
#define LOG2E 1.4426950408889634f
#define LN_EPS 1e-5f

// Scratch (device globals; no allocation allowed)
__device__ __half g_Xh[M_ * C_];
__device__ __half g_Wqh[C_ * C_];
__device__ __half g_Wkh[C_ * C_];
__device__ __half g_Wvh[C_ * C_];
__device__ __half g_Qh[M_ * C_];
__device__ __half g_Kh[M_ * C_];
__device__ __half g_Vh[M_ * C_];
__device__ __half g_Ah[M_ * C_];      // attention output (fp16)

// ---------------------------------------------------------------------------
// Helpers
// ---------------------------------------------------------------------------
__device__ __forceinline__ void mma_f16(float c[4],
                                        uint32_t a0, uint32_t a1,
                                        uint32_t a2, uint32_t a3,
                                        uint32_t b0, uint32_t b1) {
    asm volatile(
        "mma.sync.aligned.m16n8k16.row.col.f32.f16.f16.f32 "
        "{%0,%1,%2,%3},{%4,%5,%6,%7},{%8,%9},{%0,%1,%2,%3};"
        : "+f"(c[0]), "+f"(c[1]), "+f"(c[2]), "+f"(c[3])
        : "r"(a0), "r"(a1), "r"(a2), "r"(a3), "r"(b0), "r"(b1));
}

__device__ __forceinline__ void ldsm_x4(uint32_t& r0, uint32_t& r1,
                                        uint32_t& r2, uint32_t& r3,
                                        uint32_t addr) {
    asm volatile("ldmatrix.sync.aligned.m8n8.x4.shared.b16 {%0,%1,%2,%3},[%4];"
                 : "=r"(r0), "=r"(r1), "=r"(r2), "=r"(r3) : "r"(addr));
}
__device__ __forceinline__ void ldsm_x2(uint32_t& r0, uint32_t& r1,
                                        uint32_t addr) {
    asm volatile("ldmatrix.sync.aligned.m8n8.x2.shared.b16 {%0,%1},[%2];"
                 : "=r"(r0), "=r"(r1) : "r"(addr));
}
__device__ __forceinline__ void ldsm_x2t(uint32_t& r0, uint32_t& r1,
                                         uint32_t addr) {
    asm volatile("ldmatrix.sync.aligned.m8n8.x2.trans.shared.b16 {%0,%1},[%2];"
                 : "=r"(r0), "=r"(r1) : "r"(addr));
}

__device__ __forceinline__ float ex2f(float x) {
    float y;
    asm("ex2.approx.ftz.f32 %0, %1;" : "=f"(y) : "f"(x));
    return y;
}

__device__ __forceinline__ uint32_t packh2(float x, float y) {
    __half2 h = __floats2half2_rn(x, y);
    return *(uint32_t*)&h;
}

__device__ __forceinline__ void cp16(uint32_t saddr, const void* gptr) {
    asm volatile("cp.async.cg.shared.global [%0], [%1], 16;"
                 :: "r"(saddr), "l"(gptr));
}
#define CP_COMMIT() asm volatile("cp.async.commit_group;")
#define CP_WAIT1()  asm volatile("cp.async.wait_group 1;")
#define CP_WAIT0()  asm volatile("cp.async.wait_group 0;")

// ---------------------------------------------------------------------------
// Fused fp32 -> fp16 conversion: x, Wq, Wk, Wv in ONE launch.
// ---------------------------------------------------------------------------
#define NX4 (M_ * C_ / 4)   // 2097152
#define NW4 (C_ * C_ / 4)   // 262144

__global__ void __launch_bounds__(256)
cvt_all_kernel(const float* __restrict__ x,  const float* __restrict__ Wq,
               const float* __restrict__ Wk, const float* __restrict__ Wv) {
    int i = blockIdx.x * blockDim.x + threadIdx.x;
    const float* src;
    __half* dst;
    int j;
    if (i < NX4)                { src = x;  dst = g_Xh;  j = i; }
    else if (i < NX4 + NW4)     { src = Wq; dst = g_Wqh; j = i - NX4; }
    else if (i < NX4 + 2 * NW4) { src = Wk; dst = g_Wkh; j = i - NX4 - NW4; }
    else if (i < NX4 + 3 * NW4) { src = Wv; dst = g_Wvh; j = i - NX4 - 2 * NW4; }
    else return;
    float4 v = ((const float4*)src)[j];
    ((__half2*)dst)[2 * j]     = __floats2half2_rn(v.x, v.y);
    ((__half2*)dst)[2 * j + 1] = __floats2half2_rn(v.z, v.w);
}

// ---------------------------------------------------------------------------
// Fused QKV GEMM-NT (fp16 in, fp32 accum) — R12 configuration (proven).
// Block 128x128, K-chunk 64, 128 threads (4 warps, 64x64 warp tiles),
// 2-stage cp.async, per-tile ldmatrix (conflict-free). Row pitch 144B.
// ---------------------------------------------------------------------------
#define GBM 128
#define GBN 128
#define GBK 64
#define GPH 72
#define QTILE_B (GBM * GPH * 2)       // 18432 bytes per tile

__global__ void __launch_bounds__(128)
qkv_kernel(const __half* __restrict__ xh,
           const __half* __restrict__ Wq, const __half* __restrict__ Wk,
           const __half* __restrict__ Wv,
           __half* __restrict__ Qo, __half* __restrict__ Ko,
           __half* __restrict__ Vo) {
    extern __shared__ char smraw[];
    const uint32_t As_u = (uint32_t)__cvta_generic_to_shared(smraw);
    const uint32_t Bs_u = As_u + 2 * QTILE_B;

    const int z = blockIdx.z;
    const __half* W = (z == 0) ? Wq : (z == 1) ? Wk : Wv;
    __half* Cm      = (z == 0) ? Qo : (z == 1) ? Ko : Vo;

    const int tid  = threadIdx.x;
    const int warp = tid >> 5;
    const int lane = tid & 31;
    const int g = lane >> 2;
    const int q = lane & 3;
    const int wm = (warp & 1) * 64;
    const int wn = (warp >> 1) * 64;
    const int bm = blockIdx.y * GBM;
    const int bn = blockIdx.x * GBN;

    const uint32_t laneA = (uint32_t)((lane & 15) * 144 + (lane >> 4) * 16);
    const uint32_t laneB = (uint32_t)((lane & 7) * 144 + ((lane >> 3) & 1) * 16);

    float cc[4][8][4];
    #pragma unroll
    for (int mt = 0; mt < 4; mt++)
        #pragma unroll
        for (int nt = 0; nt < 8; nt++)
            #pragma unroll
            for (int e = 0; e < 4; e++) cc[mt][nt][e] = 0.f;

    auto copy_tile = [&](int st, int kt) {
        const int k0 = kt * GBK;
        const uint32_t sa = As_u + (uint32_t)st * QTILE_B;
        const uint32_t sb = Bs_u + (uint32_t)st * QTILE_B;
        #pragma unroll
        for (int i = 0; i < 8; i++) {
            int idx = i * 128 + tid;
            int r = idx >> 3;
            int c8 = (idx & 7) * 8;
            cp16(sa + (uint32_t)(r * 144 + (idx & 7) * 16),
                 xh + (size_t)(bm + r) * C_ + k0 + c8);
            cp16(sb + (uint32_t)(r * 144 + (idx & 7) * 16),
                 W + (size_t)(bn + r) * C_ + k0 + c8);
        }
    };

    const int NT = C_ / GBK;   // 16
    copy_tile(0, 0);
    CP_COMMIT();

    for (int kt = 0; kt < NT; kt++) {
        if (kt + 1 < NT) {
            copy_tile((kt + 1) & 1, kt + 1);
            CP_COMMIT();
            CP_WAIT1();
        } else {
            CP_WAIT0();
        }
        __syncthreads();

        const uint32_t a_s = As_u + (uint32_t)((kt & 1)) * QTILE_B;
        const uint32_t b_s = Bs_u + (uint32_t)((kt & 1)) * QTILE_B;

        #pragma unroll
        for (int ks = 0; ks < 4; ks++) {
            uint32_t af[4][4];
            #pragma unroll
            for (int mt = 0; mt < 4; mt++)
                ldsm_x4(af[mt][0], af[mt][1], af[mt][2], af[mt][3],
                        a_s + (uint32_t)((wm + mt * 16) * 144 + ks * 32) + laneA);
            uint32_t bf[8][2];
            #pragma unroll
            for (int nt = 0; nt < 8; nt++)
                ldsm_x2(bf[nt][0], bf[nt][1],
                        b_s + (uint32_t)((wn + nt * 8) * 144 + ks * 32) + laneB);
            #pragma unroll
            for (int mt = 0; mt < 4; mt++)
                #pragma unroll
                for (int nt = 0; nt < 8; nt++)
                    mma_f16(cc[mt][nt], af[mt][0], af[mt][1], af[mt][2],
                            af[mt][3], bf[nt][0], bf[nt][1]);
        }
        __syncthreads();
    }

    #pragma unroll
    for (int mt = 0; mt < 4; mt++) {
        int r0 = bm + wm + mt * 16 + g;
        #pragma unroll
        for (int nt = 0; nt < 8; nt++) {
            int col = bn + wn + nt * 8 + 2 * q;
            *(__half2*)(Cm + (size_t)r0 * C_ + col) =
                __floats2half2_rn(cc[mt][nt][0], cc[mt][nt][1]);
            *(__half2*)(Cm + (size_t)(r0 + 8) * C_ + col) =
                __floats2half2_rn(cc[mt][nt][2], cc[mt][nt][3]);
        }
    }
}

// ---------------------------------------------------------------------------
// Flash attention (causal), fp16 MMA + ldmatrix, P in registers — R12 config,
// output stored as fp16.
// Q tile 128 x D=64, KV tiles 64 double-buffered, 4 warps (32 rows each).
// ---------------------------------------------------------------------------
#define PS_B (128 * 144)     // 18432 bytes (Q staging only)
#define KT_B (64 * 144)      // 9216 bytes per KV stage per matrix

__global__ void __launch_bounds__(128)
attn_kernel(const __half* __restrict__ Q, const __half* __restrict__ K,
            const __half* __restrict__ V, __half* __restrict__ O_) {
    extern __shared__ char smb[];
    const uint32_t Ps_u = (uint32_t)__cvta_generic_to_shared(smb);
    const uint32_t Ks_u = Ps_u + PS_B;         // 2 x 64 x 72
    const uint32_t Vs_u = Ks_u + 2 * KT_B;     // 2 x 64 x 72

    const int qt  = (gridDim.x - 1) - blockIdx.x;   // heavy blocks first
    const int bh  = blockIdx.y;
    const int b   = bh / NH_;
    const int h   = bh % NH_;
    const int tid  = threadIdx.x;
    const int warp = tid >> 5;
    const int lane = tid & 31;
    const int g = lane >> 2;
    const int q = lane & 3;
    const int wr = warp * 32;

    const uint32_t laneA = (uint32_t)((lane & 15) * 144 + (lane >> 4) * 16);
    const uint32_t laneB = (uint32_t)((lane & 7) * 144 + ((lane >> 3) & 1) * 16);
    const uint32_t laneT = (uint32_t)((lane & 15) * 144);   // trans B (V)

    const size_t base = ((size_t)b * T_) * C_ + (size_t)h * D_;
    const int gqr = qt * 128;

    auto copy_kv = [&](int st, int kt) {
        const uint32_t sk = Ks_u + (uint32_t)st * KT_B;
        const uint32_t sv = Vs_u + (uint32_t)st * KT_B;
        #pragma unroll
        for (int i = 0; i < 4; i++) {
            int idx = i * 128 + tid;
            int r = idx >> 3;
            int c8 = (idx & 7) * 8;
            cp16(sk + (uint32_t)(r * 144 + (idx & 7) * 16),
                 K + base + (size_t)(kt * 64 + r) * C_ + c8);
            cp16(sv + (uint32_t)(r * 144 + (idx & 7) * 16),
                 V + base + (size_t)(kt * 64 + r) * C_ + c8);
        }
    };

    copy_kv(0, 0);
    CP_COMMIT();

    // stage Q (scaled into log2 domain)
    const __half2 qsh = __float2half2_rn(INV_TP * LOG2E);
    for (int i = 0; i < 8; i++) {
        int idx = i * 128 + tid;
        int r = idx >> 3;
        int d8 = (idx & 7) * 8;
        uint4 raw = *(const uint4*)(Q + base + (size_t)(gqr + r) * C_ + d8);
        __half2* hp = (__half2*)&raw;
        hp[0] = __hmul2(hp[0], qsh);
        hp[1] = __hmul2(hp[1], qsh);
        hp[2] = __hmul2(hp[2], qsh);
        hp[3] = __hmul2(hp[3], qsh);
        *(uint4*)((char*)smb + r * 144 + d8 * 2) = raw;
    }
    __syncthreads();

    // register-resident Q fragments (4 k-steps of 16)
    uint32_t qf[2][4][4];
    #pragma unroll
    for (int mt = 0; mt < 2; mt++)
        #pragma unroll
        for (int ks = 0; ks < 4; ks++)
            ldsm_x4(qf[mt][ks][0], qf[mt][ks][1], qf[mt][ks][2], qf[mt][ks][3],
                    Ps_u + (uint32_t)((wr + mt * 16) * 144 + ks * 32) + laneA);

    float o[2][8][4];
    #pragma unroll
    for (int mt = 0; mt < 2; mt++)
        #pragma unroll
        for (int nt = 0; nt < 8; nt++)
            #pragma unroll
            for (int e = 0; e < 4; e++) o[mt][nt][e] = 0.f;
    float mrow[2][2], lrow[2][2];
    #pragma unroll
    for (int mt = 0; mt < 2; mt++) {
        mrow[mt][0] = -1e30f; mrow[mt][1] = -1e30f;
        lrow[mt][0] = 0.f;    lrow[mt][1] = 0.f;
    }

    const int nkv = 2 * qt + 2;
    for (int kt = 0; kt < nkv; kt++) {
        if (kt + 1 < nkv) {
            copy_kv((kt + 1) & 1, kt + 1);
            CP_COMMIT();
            CP_WAIT1();
        } else {
            CP_WAIT0();
        }
        __syncthreads();

        const uint32_t k_s = Ks_u + (uint32_t)((kt & 1)) * KT_B;
        const uint32_t v_s = Vs_u + (uint32_t)((kt & 1)) * KT_B;
        const int c0 = kt * 64;
        const bool active = (c0 <= gqr + wr + 31);

        if (active) {
            // S = Q K^T  (A regs, B via ldmatrix; 4 k-steps of 16)
            float s[2][8][4];
            #pragma unroll
            for (int mt = 0; mt < 2; mt++)
                #pragma unroll
                for (int nt = 0; nt < 8; nt++)
                    #pragma unroll
                    for (int e = 0; e < 4; e++) s[mt][nt][e] = 0.f;

            #pragma unroll
            for (int ks = 0; ks < 4; ks++) {
                #pragma unroll
                for (int nt = 0; nt < 8; nt++) {
                    uint32_t b0, b1;
                    ldsm_x2(b0, b1,
                            k_s + (uint32_t)((nt * 8) * 144 + ks * 32) + laneB);
                    mma_f16(s[0][nt], qf[0][ks][0], qf[0][ks][1],
                            qf[0][ks][2], qf[0][ks][3], b0, b1);
                    mma_f16(s[1][nt], qf[1][ks][0], qf[1][ks][1],
                            qf[1][ks][2], qf[1][ks][3], b0, b1);
                }
            }

            // causal mask
            if (c0 + 63 > gqr + wr) {
                #pragma unroll
                for (int mt = 0; mt < 2; mt++)
                    #pragma unroll
                    for (int nt = 0; nt < 8; nt++)
                        #pragma unroll
                        for (int e = 0; e < 4; e++) {
                            int r = gqr + wr + mt * 16 + g + ((e >= 2) ? 8 : 0);
                            int c = c0 + nt * 8 + 2 * q + (e & 1);
                            if (c > r) s[mt][nt][e] = -1e30f;
                        }
            }

            // online softmax (log2 domain)
            #pragma unroll
            for (int mt = 0; mt < 2; mt++) {
                float mx0 = -1e30f, mx1 = -1e30f;
                #pragma unroll
                for (int nt = 0; nt < 8; nt++) {
                    mx0 = fmaxf(mx0, fmaxf(s[mt][nt][0], s[mt][nt][1]));
                    mx1 = fmaxf(mx1, fmaxf(s[mt][nt][2], s[mt][nt][3]));
                }
                mx0 = fmaxf(mx0, __shfl_xor_sync(0xffffffffu, mx0, 1));
                mx0 = fmaxf(mx0, __shfl_xor_sync(0xffffffffu, mx0, 2));
                mx1 = fmaxf(mx1, __shfl_xor_sync(0xffffffffu, mx1, 1));
                mx1 = fmaxf(mx1, __shfl_xor_sync(0xffffffffu, mx1, 2));
                float mn0 = fmaxf(mrow[mt][0], mx0);
                float mn1 = fmaxf(mrow[mt][1], mx1);
                float corr0 = ex2f(mrow[mt][0] - mn0);
                float corr1 = ex2f(mrow[mt][1] - mn1);
                mrow[mt][0] = mn0; mrow[mt][1] = mn1;

                float rs0 = 0.f, rs1 = 0.f;
                #pragma unroll
                for (int nt = 0; nt < 8; nt++) {
                    float p0 = ex2f(s[mt][nt][0] - mn0);
                    float p1 = ex2f(s[mt][nt][1] - mn0);
                    float p2 = ex2f(s[mt][nt][2] - mn1);
                    float p3 = ex2f(s[mt][nt][3] - mn1);
                    s[mt][nt][0] = p0; s[mt][nt][1] = p1;
                    s[mt][nt][2] = p2; s[mt][nt][3] = p3;
                    rs0 += p0 + p1; rs1 += p2 + p3;
                }
                rs0 += __shfl_xor_sync(0xffffffffu, rs0, 1);
                rs0 += __shfl_xor_sync(0xffffffffu, rs0, 2);
                rs1 += __shfl_xor_sync(0xffffffffu, rs1, 1);
                rs1 += __shfl_xor_sync(0xffffffffu, rs1, 2);
                lrow[mt][0] = lrow[mt][0] * corr0 + rs0;
                lrow[mt][1] = lrow[mt][1] * corr1 + rs1;
                #pragma unroll
                for (int nt = 0; nt < 8; nt++) {
                    o[mt][nt][0] *= corr0; o[mt][nt][1] *= corr0;
                    o[mt][nt][2] *= corr1; o[mt][nt][3] *= corr1;
                }
            }

            // O += P @ V  — P A-fragments built directly from S registers
            #pragma unroll
            for (int ks = 0; ks < 4; ks++) {
                uint32_t a[2][4];
                #pragma unroll
                for (int mt = 0; mt < 2; mt++) {
                    a[mt][0] = packh2(s[mt][2 * ks][0],     s[mt][2 * ks][1]);
                    a[mt][1] = packh2(s[mt][2 * ks][2],     s[mt][2 * ks][3]);
                    a[mt][2] = packh2(s[mt][2 * ks + 1][0], s[mt][2 * ks + 1][1]);
                    a[mt][3] = packh2(s[mt][2 * ks + 1][2], s[mt][2 * ks + 1][3]);
                }
                #pragma unroll
                for (int nt = 0; nt < 8; nt++) {
                    uint32_t b0, b1;
                    ldsm_x2t(b0, b1,
                             v_s + (uint32_t)(ks * 16 * 144 + nt * 16) + laneT);
                    mma_f16(o[0][nt], a[0][0], a[0][1], a[0][2], a[0][3], b0, b1);
                    mma_f16(o[1][nt], a[1][0], a[1][1], a[1][2], a[1][3], b0, b1);
                }
            }
        }
        __syncthreads();
    }

    // epilogue: normalize and store (fp16)
    #pragma unroll
    for (int mt = 0; mt < 2; mt++) {
        float inv0 = 1.f / lrow[mt][0];
        float inv1 = 1.f / lrow[mt][1];
        int r0 = gqr + wr + mt * 16 + g;
        #pragma unroll
        for (int nt = 0; nt < 8; nt++) {
            int col = nt * 8 + 2 * q;
            *(__half2*)(O_ + base + (size_t)r0 * C_ + col) =
                __floats2half2_rn(o[mt][nt][0] * inv0, o[mt][nt][1] * inv0);
            *(__half2*)(O_ + base + (size_t)(r0 + 8) * C_ + col) =
                __floats2half2_rn(o[mt][nt][2] * inv1, o[mt][nt][3] * inv1);
        }
    }
}

// ---------------------------------------------------------------------------
// Residual + LayerNorm. One block per row; attn input is fp16.
// ---------------------------------------------------------------------------
__global__ void __launch_bounds__(256)
ln_kernel(const float* __restrict__ x, const __half* __restrict__ attn,
          const float* __restrict__ gamma, const float* __restrict__ beta,
          float* __restrict__ out) {
    __shared__ float buf[C_];
    __shared__ float s1[8], s2[8];

    const int row = blockIdx.x;
    const int t = threadIdx.x;
    const float4 xa = ((const float4*)(x + (size_t)row * C_))[t];
    // 4 halves = one uint2
    const uint2 ar = ((const uint2*)(attn + (size_t)row * C_))[t];
    const __half2 a01 = *(const __half2*)&ar.x;
    const __half2 a23 = *(const __half2*)&ar.y;
    float4 y;
    y.x = xa.x + __low2float(a01);  y.y = xa.y + __high2float(a01);
    y.z = xa.z + __low2float(a23);  y.w = xa.w + __high2float(a23);
    ((float4*)buf)[t] = y;

    float lsum = y.x + y.y + y.z + y.w;
    float lsq  = y.x * y.x + y.y * y.y + y.z * y.z + y.w * y.w;
    #pragma unroll
    for (int off = 16; off; off >>= 1) {
        lsum += __shfl_xor_sync(0xffffffffu, lsum, off);
        lsq  += __shfl_xor_sync(0xffffffffu, lsq,  off);
    }
    const int wid = t >> 5, lane = t & 31;
    if (lane == 0) { s1[wid] = lsum; s2[wid] = lsq; }
    __syncthreads();
    if (t == 0) {
        float a = 0.f, b2 = 0.f;
        #pragma unroll
        for (int i = 0; i < 8; i++) { a += s1[i]; b2 += s2[i]; }
        s1[0] = a; s2[0] = b2;
    }
    __syncthreads();
    const float mean = s1[0] * (1.f / C_);
    const float var  = s2[0] * (1.f / C_) - mean * mean;
    const float inv  = rsqrtf(var + LN_EPS);

    const float4 yv = ((const float4*)buf)[t];
    const float4 gg = ((const float4*)gamma)[t];
    const float4 bb = ((const float4*)beta)[t];
    float4 oo;
    oo.x = (yv.x - mean) * inv * gg.x + bb.x;
    oo.y = (yv.y - mean) * inv * gg.y + bb.y;
    oo.z = (yv.z - mean) * inv * gg.z + bb.z;
    oo.w = (yv.w - mean) * inv * gg.w + bb.w;
    ((float4*)(out + (size_t)row * C_))[t] = oo;
}

// ---------------------------------------------------------------------------
// Launcher
// ---------------------------------------------------------------------------
extern "C" void kernel_launch(void* const* d_in, const int* in_sizes, int n_in,
                              void* d_out, int out_size) {
    const float* x     = (const float*)d_in[0];
    // d_in[1] = mask (bool) — causal, applied analytically in-kernel
    const float* Wq    = (const float*)d_in[2];
    const float* Wk    = (const float*)d_in[3];
    const float* Wv    = (const float*)d_in[4];
    const float* gamma = (const float*)d_in[5];
    const float* beta  = (const float*)d_in[6];
    float* out = (float*)d_out;

    __half *xh, *wqh, *wkh, *wvh, *qh, *kh, *vh, *ah;
    cudaGetSymbolAddress((void**)&xh,  g_Xh);
    cudaGetSymbolAddress((void**)&wqh, g_Wqh);
    cudaGetSymbolAddress((void**)&wkh, g_Wkh);
    cudaGetSymbolAddress((void**)&wvh, g_Wvh);
    cudaGetSymbolAddress((void**)&qh,  g_Qh);
    cudaGetSymbolAddress((void**)&kh,  g_Kh);
    cudaGetSymbolAddress((void**)&vh,  g_Vh);
    cudaGetSymbolAddress((void**)&ah,  g_Ah);

    // fp32 -> fp16 prologue (single fused launch)
    const int ntot = NX4 + 3 * NW4;
    cvt_all_kernel<<<(ntot + 255) / 256, 256>>>(x, Wq, Wk, Wv);

    const int gemm_smem = 4 * QTILE_B;  // 73728 B
    cudaFuncSetAttribute(qkv_kernel, cudaFuncAttributeMaxDynamicSharedMemorySize,
                         gemm_smem);
    qkv_kernel<<<dim3(C_ / GBN, M_ / GBM, 3), 128, gemm_smem>>>(
        xh, wqh, wkh, wvh, qh, kh, vh);

    const int attn_smem = PS_B + 4 * KT_B;  // 55296 B
    cudaFuncSetAttribute(attn_kernel, cudaFuncAttributeMaxDynamicSharedMemorySize,
                         attn_smem);
    attn_kernel<<<dim3(T_ / 128, B_ * NH_), 128, attn_smem>>>(qh, kh, vh, ah);

    ln_kernel<<<M_, 256>>>(x, ah, gamma, beta, out);
}